// round 5
// baseline (speedup 1.0000x reference)
#include <cuda_runtime.h>
#include <cuda_bf16.h>
#include <math.h>

// ---------------------------------------------------------------------------
// Problem constants
// ---------------------------------------------------------------------------
#define BB    1024
#define TENC  128
#define TDEC  64
#define HH    128
#define FF    16
#define SS    8
#define HE    256           // encoder hidden
#define HD    132           // decoder hidden
#define SB    (SS*BB)       // 8192 decoder effective batch
#define TT    (TENC+TDEC)   // 192 features time dim
#define DEC_BASE 2080768    // 8*1024*127*2
#define ENC_SSTRIDE 260096  // 1024*127*2

// ---------------------------------------------------------------------------
// Device scratch (no allocations allowed)
// ---------------------------------------------------------------------------
__device__ float g_h0[2 * BB * HE];            // encoder layer0 ping-pong
__device__ float g_h1[2 * BB * HE];            // encoder layer1 ping-pong
__device__ float g_enc[TENC * BB * HH];        // masked layer1 outputs (t, b, 128)
__device__ float g_last[BB * 2];
__device__ float g_dh0[2 * SB * HD];           // decoder layer0 ping-pong
__device__ float g_dh1[2 * SB * HD];           // decoder layer1 ping-pong
__device__ float g_dout[SB * 2];               // decoder step output / next input

// ---------------------------------------------------------------------------
// Helpers
// ---------------------------------------------------------------------------
__device__ __forceinline__ float sigm(float x) { return 1.f / (1.f + expf(-x)); }
__device__ __forceinline__ float softp(float x) {
    return fmaxf(x, 0.f) + log1pf(expf(-fabsf(x)));
}

// ---------------------------------------------------------------------------
// Generic accumulation pass: adds act(64 rows) @ W(3 gates x 32 cols)^T
// into per-thread accumulators. K chunked by 64 through shared memory.
//   act row r: act + (rb0+r)*actStride, entries [kc, kc+64) clipped to kdim
//   W gate-g row j: W + (g*whid + j)*wstride, same k window
// ---------------------------------------------------------------------------
__device__ __forceinline__ void accum_pass(
    float* h_sm, float* w_sm,
    const float* __restrict__ act, long actStride, int kdim,
    const float* __restrict__ W, int wstride, int whid,
    int jt0, int rb0, int lane, int warp, int tid,
    float* aR, float* aZ, float* aN)
{
    for (int kc = 0; kc < kdim; kc += 64) {
        // stage activations: 64 rows x 64 k (stride 68)
        for (int idx = tid; idx < 64 * 64; idx += 256) {
            int r = idx >> 6, k = idx & 63;
            int kg = kc + k;
            h_sm[r * 68 + k] = (kg < kdim)
                ? act[(long)(rb0 + r) * actStride + kg] : 0.f;
        }
        // stage weights: 3 gates x 32 cols x 64 k (stride 68)
        for (int idx = tid; idx < 96 * 64; idx += 256) {
            int rr = idx >> 6, k = idx & 63;
            int g = rr >> 5, jj = rr & 31;
            int j = jt0 + jj;
            int kg = kc + k;
            w_sm[rr * 68 + k] = (j < whid && kg < kdim)
                ? W[((long)g * whid + j) * wstride + kg] : 0.f;
        }
        __syncthreads();

        const float* wr = w_sm + lane * 68;
        const float* wz = w_sm + (32 + lane) * 68;
        const float* wn = w_sm + (64 + lane) * 68;
        const float* hb = h_sm + warp * 8 * 68;

        #pragma unroll 4
        for (int k = 0; k < 64; k += 4) {
            float4 w4r = *(const float4*)(wr + k);
            float4 w4z = *(const float4*)(wz + k);
            float4 w4n = *(const float4*)(wn + k);
            #pragma unroll
            for (int i = 0; i < 8; i++) {
                float4 h4 = *(const float4*)(hb + i * 68 + k);
                aR[i] = fmaf(h4.x, w4r.x, aR[i]);
                aR[i] = fmaf(h4.y, w4r.y, aR[i]);
                aR[i] = fmaf(h4.z, w4r.z, aR[i]);
                aR[i] = fmaf(h4.w, w4r.w, aR[i]);
                aZ[i] = fmaf(h4.x, w4z.x, aZ[i]);
                aZ[i] = fmaf(h4.y, w4z.y, aZ[i]);
                aZ[i] = fmaf(h4.z, w4z.z, aZ[i]);
                aZ[i] = fmaf(h4.w, w4z.w, aZ[i]);
                aN[i] = fmaf(h4.x, w4n.x, aN[i]);
                aN[i] = fmaf(h4.y, w4n.y, aN[i]);
                aN[i] = fmaf(h4.z, w4n.z, aN[i]);
                aN[i] = fmaf(h4.w, w4n.w, aN[i]);
            }
        }
        __syncthreads();
    }
}

// ---------------------------------------------------------------------------
// Fused GRU step: Hnext = GRUCell(concat(XA, XB), Hprev), optional mask,
// optional masked-output store of first 128 dims.
// grid = (batch/64, ceil(hid/32)), block = 256
// ---------------------------------------------------------------------------
__global__ __launch_bounds__(256) void k_gru(
    const float* __restrict__ Hprev, float* __restrict__ Hnext,
    const float* __restrict__ XA, int dimA, long strideA,
    const float* __restrict__ XB, int dimB, long strideB,
    const float* __restrict__ Wih, const float* __restrict__ Whh,
    const float* __restrict__ bih, const float* __restrict__ bhh,
    const int* __restrict__ mask, int maskStride,
    float* __restrict__ mOut,
    int hid)
{
    __shared__ __align__(16) float h_sm[64 * 68];
    __shared__ __align__(16) float w_sm[96 * 68];

    int tid = threadIdx.x, lane = tid & 31, warp = tid >> 5;
    int rb0 = blockIdx.x * 64, jt0 = blockIdx.y * 32;
    int j = jt0 + lane;
    int in_dim = dimA + dimB;

    float aR[8], aZ[8], aNi[8], aNh[8];
    #pragma unroll
    for (int i = 0; i < 8; i++) { aR[i] = 0.f; aZ[i] = 0.f; aNi[i] = 0.f; aNh[i] = 0.f; }

    // hidden path
    accum_pass(h_sm, w_sm, Hprev, hid, hid, Whh, hid, hid,
               jt0, rb0, lane, warp, tid, aR, aZ, aNh);
    // input path A
    accum_pass(h_sm, w_sm, XA, strideA, dimA, Wih, in_dim, hid,
               jt0, rb0, lane, warp, tid, aR, aZ, aNi);
    // input path B (optional)
    if (dimB > 0)
        accum_pass(h_sm, w_sm, XB, strideB, dimB, Wih + dimA, in_dim, hid,
                   jt0, rb0, lane, warp, tid, aR, aZ, aNi);

    if (j < hid) {
        float bR  = bih[j] + bhh[j];
        float bZ  = bih[hid + j] + bhh[hid + j];
        float bNi = bih[2 * hid + j];
        float bNh = bhh[2 * hid + j];
        #pragma unroll
        for (int i = 0; i < 8; i++) {
            int row = rb0 + warp * 8 + i;
            float hold = Hprev[(long)row * hid + j];
            float r = sigm(aR[i] + bR);
            float z = sigm(aZ[i] + bZ);
            float n = tanhf(aNi[i] + bNi + r * (aNh[i] + bNh));
            float hn = (1.f - z) * n + z * hold;
            int mval = mask ? mask[(long)row * maskStride] : 1;
            float hfin = mval ? hn : hold;
            Hnext[(long)row * hid + j] = hfin;
            if (mOut && j < HH)
                mOut[(long)row * HH + j] = mval ? hfin : 0.f;
        }
    }
}

// ---------------------------------------------------------------------------
// MLP: softplus(relu(h @ W1^T + b1) @ W2^T + b2), 16 rows per block.
// mode 0: encoder (rows over (t,b), writes broadcast enc output + g_last + dec t=0)
// mode 1: decoder step tstep (rows over (s,b), writes g_dout + dec output)
// ---------------------------------------------------------------------------
__global__ __launch_bounds__(256) void k_mlp(
    const float* __restrict__ Hin, int hstride,
    const float* __restrict__ W1, const float* __restrict__ b1,
    const float* __restrict__ W2, const float* __restrict__ b2,
    float* __restrict__ outb, float* __restrict__ dout,
    float* __restrict__ glast, int mode, int tstep)
{
    __shared__ __align__(16) float w1s[64 * 132];
    __shared__ __align__(16) float hs[16 * 132];
    __shared__ float h1s[16 * 68];
    __shared__ float w2s[128];
    __shared__ float b1s[64];
    __shared__ float b2s[2];

    int tid = threadIdx.x;
    int row0 = blockIdx.x * 16;

    for (int idx = tid; idx < 64 * 128; idx += 256) {
        int o = idx >> 7, k = idx & 127;
        w1s[o * 132 + k] = W1[idx];
    }
    for (int idx = tid; idx < 16 * 128; idx += 256) {
        int rr = idx >> 7, k = idx & 127;
        hs[rr * 132 + k] = Hin[(long)(row0 + rr) * hstride + k];
    }
    if (tid < 128) w2s[tid] = W2[tid];
    if (tid < 64)  b1s[tid] = b1[tid];
    if (tid < 2)   b2s[tid] = b2[tid];
    __syncthreads();

    #pragma unroll
    for (int p = 0; p < 4; p++) {
        int idx = p * 256 + tid;
        int o = idx & 63, rr = idx >> 6;
        const float* wp = w1s + o * 132;
        const float* hp = hs + rr * 132;
        float acc = b1s[o];
        #pragma unroll 8
        for (int k = 0; k < 128; k += 4) {
            float4 w4 = *(const float4*)(wp + k);
            float4 h4 = *(const float4*)(hp + k);
            acc = fmaf(w4.x, h4.x, acc);
            acc = fmaf(w4.y, h4.y, acc);
            acc = fmaf(w4.z, h4.z, acc);
            acc = fmaf(w4.w, h4.w, acc);
        }
        h1s[rr * 68 + o] = fmaxf(acc, 0.f);
    }
    __syncthreads();

    if (tid < 32) {
        int rr = tid >> 1, c = tid & 1;
        const float* hp = h1s + rr * 68;
        const float* wp = w2s + c * 64;
        float acc = b2s[c];
        #pragma unroll 8
        for (int k = 0; k < 64; k++) acc = fmaf(hp[k], wp[k], acc);
        float pred = softp(acc);
        int row = row0 + rr;
        if (mode == 0) {
            int t = row >> 10, b = row & 1023;
            if (t < 127) {
                long off = (long)b * 254 + t * 2 + c;
                #pragma unroll
                for (int s = 0; s < SS; s++)
                    outb[(long)s * ENC_SSTRIDE + off] = pred;
            } else {
                glast[b * 2 + c] = pred;
                #pragma unroll
                for (int s = 0; s < SS; s++)
                    outb[DEC_BASE + (long)((s << 10) | b) * 128 + c] = pred;
            }
        } else {
            dout[row * 2 + c] = pred;
            outb[DEC_BASE + (long)row * 128 + tstep * 2 + c] = pred;
        }
    }
}

// ---------------------------------------------------------------------------
// Reparameterization + decoder initial hidden states
// dh{0,1}[(s*B+b)*132 + j]:  j<128: eps[s,l,b,j]*exp(0.5*logvar)+mean
//                            j>=128: features[b,128, j-128]
// ---------------------------------------------------------------------------
__global__ void k_z(
    const float* __restrict__ hf0, const float* __restrict__ hf1,
    const float* __restrict__ eps, const float* __restrict__ feat,
    float* __restrict__ dh0, float* __restrict__ dh1)
{
    int idx = blockIdx.x * blockDim.x + threadIdx.x;
    if (idx >= SB * HD) return;
    int row = idx / HD, j = idx - row * HD;
    int s = row >> 10, b = row & 1023;
    float v0, v1;
    if (j < HH) {
        float m0 = hf0[b * HE + j],      lv0 = hf0[b * HE + HH + j];
        float m1 = hf1[b * HE + j],      lv1 = hf1[b * HE + HH + j];
        float e0 = eps[(((long)(s * 2 + 0) * BB + b) * HH) + j];
        float e1 = eps[(((long)(s * 2 + 1) * BB + b) * HH) + j];
        v0 = e0 * expf(0.5f * lv0) + m0;
        v1 = e1 * expf(0.5f * lv1) + m1;
    } else {
        float fc = feat[((long)b * TT + TENC) * FF + (j - HH)];
        v0 = fc; v1 = fc;
    }
    dh0[idx] = v0;
    dh1[idx] = v1;
}

__global__ void k_bcast_last(const float* __restrict__ last, float* __restrict__ dout)
{
    int i = blockIdx.x * blockDim.x + threadIdx.x;
    if (i < SB * 2) {
        int row = i >> 1, c = i & 1;
        dout[i] = last[((row & 1023) << 1) | c];
    }
}

__global__ void k_zero2(float* a, float* b, int n)
{
    int i = blockIdx.x * blockDim.x + threadIdx.x;
    if (i < n) { a[i] = 0.f; b[i] = 0.f; }
}

// ---------------------------------------------------------------------------
// Host orchestration (graph-capturable: kernel launches only)
// ---------------------------------------------------------------------------
extern "C" void kernel_launch(void* const* d_in, const int* in_sizes, int n_in,
                              void* d_out, int out_size)
{
    const float* x    = (const float*)d_in[0];
    const float* feat = (const float*)d_in[1];
    const int*   mask = (const int*)d_in[2];
    const float* eps  = (const float*)d_in[3];

    // scalar inputs (nsteps_encode/decode, n_elbo_samp) may or may not be
    // materialized; detect by element count.
    int base = (n_in > 7 && in_sizes[4] == 1) ? 7 : 4;
    const float* eWih0 = (const float*)d_in[base + 0];
    const float* eWhh0 = (const float*)d_in[base + 1];
    const float* ebih0 = (const float*)d_in[base + 2];
    const float* ebhh0 = (const float*)d_in[base + 3];
    const float* eWih1 = (const float*)d_in[base + 4];
    const float* eWhh1 = (const float*)d_in[base + 5];
    const float* ebih1 = (const float*)d_in[base + 6];
    const float* ebhh1 = (const float*)d_in[base + 7];
    const float* dWih0 = (const float*)d_in[base + 8];
    const float* dWhh0 = (const float*)d_in[base + 9];
    const float* dbih0 = (const float*)d_in[base + 10];
    const float* dbhh0 = (const float*)d_in[base + 11];
    const float* dWih1 = (const float*)d_in[base + 12];
    const float* dWhh1 = (const float*)d_in[base + 13];
    const float* dbih1 = (const float*)d_in[base + 14];
    const float* dbhh1 = (const float*)d_in[base + 15];
    const float* W1    = (const float*)d_in[base + 16];
    const float* b1    = (const float*)d_in[base + 17];
    const float* W2    = (const float*)d_in[base + 18];
    const float* b2    = (const float*)d_in[base + 19];

    float* outb = (float*)d_out;

    float *p_h0, *p_h1, *p_enc, *p_last, *p_dh0, *p_dh1, *p_dout;
    cudaGetSymbolAddress((void**)&p_h0,   g_h0);
    cudaGetSymbolAddress((void**)&p_h1,   g_h1);
    cudaGetSymbolAddress((void**)&p_enc,  g_enc);
    cudaGetSymbolAddress((void**)&p_last, g_last);
    cudaGetSymbolAddress((void**)&p_dh0,  g_dh0);
    cudaGetSymbolAddress((void**)&p_dh1,  g_dh1);
    cudaGetSymbolAddress((void**)&p_dout, g_dout);

    const int HSZ = BB * HE;          // 262144
    const int DSZ = SB * HD;          // 1081344

    // zero initial encoder hidden states (ping slot 0)
    k_zero2<<<(HSZ + 255) / 256, 256>>>(p_h0, p_h1, HSZ);

    // ---------------- encoder scan ----------------
    float* h0c = p_h0;        float* h0n = p_h0 + HSZ;
    float* h1c = p_h1;        float* h1n = p_h1 + HSZ;
    dim3 egrid(BB / 64, HE / 32);   // (16, 8)
    for (int t = 0; t < TENC; t++) {
        // layer 0: input = concat(x[:,t,:], features[:,t,:])
        k_gru<<<egrid, 256>>>(h0c, h0n,
                              x + (long)t * 2, 2, (long)TENC * 2,
                              feat + (long)t * FF, FF, (long)TT * FF,
                              eWih0, eWhh0, ebih0, ebhh0,
                              mask + t, TENC, (float*)nullptr, HE);
        // layer 1: input = new h0
        k_gru<<<egrid, 256>>>(h1c, h1n,
                              h0n, HE, (long)HE,
                              (const float*)nullptr, 0, 0L,
                              eWih1, eWhh1, ebih1, ebhh1,
                              mask + t, TENC,
                              p_enc + (long)t * BB * HH, HE);
        float* tmp;
        tmp = h0c; h0c = h0n; h0n = tmp;
        tmp = h1c; h1c = h1n; h1n = tmp;
    }
    // final hidden states now in h0c / h1c

    // ---------------- reparameterize + encoder MLP ----------------
    k_z<<<(SB * HD + 255) / 256, 256>>>(h0c, h1c, eps, feat, p_dh0, p_dh1);
    k_mlp<<<(TENC * BB) / 16, 256>>>(p_enc, HH, W1, b1, W2, b2,
                                     outb, (float*)nullptr, p_last, 0, 0);
    k_bcast_last<<<(SB * 2 + 255) / 256, 256>>>(p_last, p_dout);

    // ---------------- decoder scan ----------------
    float* d0c = p_dh0;       float* d0n = p_dh0 + DSZ;
    float* d1c = p_dh1;       float* d1n = p_dh1 + DSZ;
    dim3 dgrid(SB / 64, (HD + 31) / 32);   // (128, 5)
    for (int t = 1; t < TDEC; t++) {
        k_gru<<<dgrid, 256>>>(d0c, d0n,
                              p_dout, 2, 2L,
                              (const float*)nullptr, 0, 0L,
                              dWih0, dWhh0, dbih0, dbhh0,
                              (const int*)nullptr, 0, (float*)nullptr, HD);
        k_gru<<<dgrid, 256>>>(d1c, d1n,
                              d0n, HD, (long)HD,
                              (const float*)nullptr, 0, 0L,
                              dWih1, dWhh1, dbih1, dbhh1,
                              (const int*)nullptr, 0, (float*)nullptr, HD);
        k_mlp<<<SB / 16, 256>>>(d1n, HD, W1, b1, W2, b2,
                                outb, p_dout, (float*)nullptr, 1, t);
        float* tmp;
        tmp = d0c; d0c = d0n; d0n = tmp;
        tmp = d1c; d1c = d1n; d1n = tmp;
    }
}

// round 7
// speedup vs baseline: 1.4791x; 1.4791x over previous
#include <cuda_runtime.h>
#include <cuda_bf16.h>
#include <math.h>

// ---------------------------------------------------------------------------
// Problem constants
// ---------------------------------------------------------------------------
#define BB    1024
#define TENC  128
#define TDEC  64
#define HH    128
#define FF    16
#define SS    8
#define HE    256
#define HD    132
#define SB    (SS*BB)
#define TT    (TENC+TDEC)
#define DEC_BASE 2080768    // 8*1024*127*2
#define ENC_SSTRIDE 260096  // 1024*127*2

typedef unsigned long long ull;

// ---------------------------------------------------------------------------
// Device scratch (16B-aligned for cp.async / vector loads)
// ---------------------------------------------------------------------------
__device__ __align__(128) float g_h0[2 * BB * HE];
__device__ __align__(128) float g_h1[2 * BB * HE];
__device__ __align__(128) float g_enc[TENC * BB * HH];
__device__ __align__(128) float g_last[BB * 2];
__device__ __align__(128) float g_dh0[2 * SB * HD];
__device__ __align__(128) float g_dh1[2 * SB * HD];
__device__ __align__(128) float g_dout[SB * 2];

// ---------------------------------------------------------------------------
// Helpers
// ---------------------------------------------------------------------------
__device__ __forceinline__ float sigm(float x) { return 1.f / (1.f + expf(-x)); }
__device__ __forceinline__ float softp(float x) {
    return fmaxf(x, 0.f) + log1pf(expf(-fabsf(x)));
}
__device__ __forceinline__ void fma2(ull &d, ull a, ull b) {
    asm("fma.rn.f32x2 %0, %1, %2, %0;" : "+l"(d) : "l"(a), "l"(b));
}
__device__ __forceinline__ float hsum2(ull v) {
    float lo = __uint_as_float((unsigned)(v & 0xffffffffull));
    float hi = __uint_as_float((unsigned)(v >> 32));
    return lo + hi;
}
__device__ __forceinline__ void cpa16(float* dst, const float* src) {
    unsigned sa = (unsigned)__cvta_generic_to_shared(dst);
    asm volatile("cp.async.cg.shared.global [%0], [%1], 16;\n" :: "r"(sa), "l"(src));
}
__device__ __forceinline__ void cpa_commit() { asm volatile("cp.async.commit_group;\n"); }
template<int N> __device__ __forceinline__ void cpa_wait() {
    asm volatile("cp.async.wait_group %0;\n" :: "n"(N));
}

// ---------------------------------------------------------------------------
// Shared-memory buffer layout (double buffered):
//   buffer = [ h: 32 rows x 68 | w: 96 rows x 68 ]  = 8704 floats
#define SM_HW   2176          // 32*68 (w region offset within buffer)
#define SM_BUF  8704          // floats per buffer
#define SM_BYTES (2 * SM_BUF * 4)   // 69632

// Stage one K-chunk (64 wide) of activations (32 rows) + weights (3x32 rows).
// Fast path: full chunk, 16B-aligned rows -> cp.async (2048 x 16B transfers).
// Slow path (partial final chunk): guarded scalar STS.
__device__ __forceinline__ void stage_chunk(
    float* buf,
    const float* __restrict__ act, long actStride, int kdim,
    const float* __restrict__ W, int wstride, int whid,
    int jt0, int rb0, int kc, int tid)
{
    float* hbuf = buf;
    float* wbuf = buf + SM_HW;
    if (kc + 64 <= kdim) {
        // h: 32 rows * 16 float4  = 512 transfers
        // w: 96 rows * 16 float4  = 1536 transfers
        for (int idx = tid; idx < 2048; idx += 256) {
            if (idx < 512) {
                int r = idx >> 4, q = idx & 15;
                cpa16(hbuf + r * 68 + q * 4,
                      act + (long)(rb0 + r) * actStride + kc + q * 4);
            } else {
                int wv = idx - 512;
                int rr = wv >> 4, q = wv & 15;
                int j = jt0 + (rr & 31);
                if (j < whid) {
                    cpa16(wbuf + rr * 68 + q * 4,
                          W + ((long)(rr >> 5) * whid + j) * wstride + kc + q * 4);
                } else {
                    float4 z = {0.f, 0.f, 0.f, 0.f};
                    *(float4*)(wbuf + rr * 68 + q * 4) = z;
                }
            }
        }
    } else {
        for (int idx = tid; idx < 2048; idx += 256) {
            int r = idx >> 6, k = idx & 63;
            int kg = kc + k;
            hbuf[r * 68 + k] = (kg < kdim)
                ? act[(long)(rb0 + r) * actStride + kg] : 0.f;
        }
        for (int idx = tid; idx < 6144; idx += 256) {
            int rr = idx >> 6, k = idx & 63;
            int kg = kc + k;
            int j = jt0 + (rr & 31);
            wbuf[rr * 68 + k] = (j < whid && kg < kdim)
                ? W[((long)(rr >> 5) * whid + j) * wstride + kg] : 0.f;
        }
    }
}

// Compute one staged chunk: 4 rows x (r,z,n) per thread, packed f32x2.
__device__ __forceinline__ void compute_chunk(
    const float* hb, const float* wr, const float* wz, const float* wn,
    int klim, ull* aR, ull* aZ, ull* aN)
{
#define CK_BODY(k) { \
    ulonglong2 r2 = *(const ulonglong2*)(wr + (k)); \
    ulonglong2 z2 = *(const ulonglong2*)(wz + (k)); \
    ulonglong2 n2 = *(const ulonglong2*)(wn + (k)); \
    _Pragma("unroll") \
    for (int i = 0; i < 4; i++) { \
        ulonglong2 h2 = *(const ulonglong2*)(hb + i * 68 + (k)); \
        fma2(aR[i], h2.x, r2.x); fma2(aR[i], h2.y, r2.y); \
        fma2(aZ[i], h2.x, z2.x); fma2(aZ[i], h2.y, z2.y); \
        fma2(aN[i], h2.x, n2.x); fma2(aN[i], h2.y, n2.y); \
    } }
    if (klim == 64) {
        #pragma unroll 8
        for (int k = 0; k < 64; k += 4) CK_BODY(k)
    } else {
        for (int k = 0; k < klim; k += 4) CK_BODY(k)
    }
#undef CK_BODY
}

// Full accumulation pass through shared memory (double-buffered, cp.async).
__device__ __forceinline__ void accum_smem(
    float* sm,
    const float* __restrict__ act, long actStride, int kdim,
    const float* __restrict__ W, int wstride, int whid,
    int jt0, int rb0, int tid, int lane, int warp,
    ull* aR, ull* aZ, ull* aN)
{
    int nch = (kdim + 63) >> 6;
    stage_chunk(sm, act, actStride, kdim, W, wstride, whid, jt0, rb0, 0, tid);
    cpa_commit();
    for (int c = 0; c < nch; c++) {
        float* cur = sm + (c & 1) * SM_BUF;
        if (c + 1 < nch) {
            stage_chunk(sm + ((c + 1) & 1) * SM_BUF, act, actStride, kdim,
                        W, wstride, whid, jt0, rb0, (c + 1) * 64, tid);
            cpa_commit();
            cpa_wait<1>();
        } else {
            cpa_wait<0>();
        }
        __syncthreads();
        int klim = kdim - c * 64;
        if (klim > 64) klim = 64;
        klim = (klim + 3) & ~3;
        compute_chunk(cur + warp * 4 * 68,
                      cur + SM_HW + lane * 68,
                      cur + SM_HW + (32 + lane) * 68,
                      cur + SM_HW + (64 + lane) * 68,
                      klim, aR, aZ, aN);
        __syncthreads();
    }
}

// Direct gmem pass for small input dims (<=32): no smem, scalar fp32.
__device__ __forceinline__ void accum_direct(
    const float* __restrict__ act, long actStride, int kdim,
    const float* __restrict__ W, int wstride, int whid,
    int j, int row0, float* gR, float* gZ, float* gN)
{
    if (j >= whid) return;
    for (int k = 0; k < kdim; k++) {
        float wr = W[(long)j * wstride + k];
        float wz = W[((long)whid + j) * wstride + k];
        float wn = W[((long)2 * whid + j) * wstride + k];
        #pragma unroll
        for (int i = 0; i < 4; i++) {
            float xv = act[(long)(row0 + i) * actStride + k];
            gR[i] = fmaf(xv, wr, gR[i]);
            gZ[i] = fmaf(xv, wz, gZ[i]);
            gN[i] = fmaf(xv, wn, gN[i]);
        }
    }
}

// ---------------------------------------------------------------------------
// Fused GRU step. grid = (batch/32, ceil(hid/32)), block = 256, dyn smem.
// ---------------------------------------------------------------------------
__global__ __launch_bounds__(256, 2) void k_gru(
    const float* __restrict__ Hprev, float* __restrict__ Hnext,
    const float* __restrict__ XA, int dimA, long strideA,
    const float* __restrict__ XB, int dimB, long strideB,
    const float* __restrict__ Wih, const float* __restrict__ Whh,
    const float* __restrict__ bih, const float* __restrict__ bhh,
    const int* __restrict__ mask, int maskStride,
    float* __restrict__ mOut, int hid)
{
    extern __shared__ __align__(16) float sm[];
    int tid = threadIdx.x, lane = tid & 31, warp = tid >> 5;
    int rb0 = blockIdx.x * 32, jt0 = blockIdx.y * 32;
    int j = jt0 + lane;
    int row0 = rb0 + warp * 4;
    int in_dim = dimA + dimB;

    ull aR[4]  = {0,0,0,0}, aZ[4]  = {0,0,0,0};
    ull aNh[4] = {0,0,0,0}, aNi[4] = {0,0,0,0};
    float gR[4] = {0,0,0,0}, gZ[4] = {0,0,0,0}, gN[4] = {0,0,0,0};

    // hidden path (always through smem, packed)
    accum_smem(sm, Hprev, hid, hid, Whh, hid, hid,
               jt0, rb0, tid, lane, warp, aR, aZ, aNh);
    // input path A
    if (dimA > 32)
        accum_smem(sm, XA, strideA, dimA, Wih, in_dim, hid,
                   jt0, rb0, tid, lane, warp, aR, aZ, aNi);
    else
        accum_direct(XA, strideA, dimA, Wih, in_dim, hid, j, row0, gR, gZ, gN);
    // input path B (optional, always small)
    if (dimB > 0)
        accum_direct(XB, strideB, dimB, Wih + dimA, in_dim, hid, j, row0, gR, gZ, gN);

    if (j < hid) {
        float bR  = bih[j] + bhh[j];
        float bZ  = bih[hid + j] + bhh[hid + j];
        float bNi = bih[2 * hid + j];
        float bNh = bhh[2 * hid + j];
        #pragma unroll
        for (int i = 0; i < 4; i++) {
            int row = row0 + i;
            float hold = Hprev[(long)row * hid + j];
            float r = sigm(hsum2(aR[i]) + gR[i] + bR);
            float z = sigm(hsum2(aZ[i]) + gZ[i] + bZ);
            float n = tanhf(hsum2(aNi[i]) + gN[i] + bNi + r * (hsum2(aNh[i]) + bNh));
            float hn = (1.f - z) * n + z * hold;
            int mv = mask ? mask[(long)row * maskStride] : 1;
            float hf = mv ? hn : hold;
            Hnext[(long)row * hid + j] = hf;
            if (mOut && j < HH)
                mOut[(long)row * HH + j] = mv ? hf : 0.f;
        }
    }
}

// ---------------------------------------------------------------------------
// MLP: softplus(relu(h @ W1^T + b1) @ W2^T + b2), 16 rows per block.
// ---------------------------------------------------------------------------
__global__ __launch_bounds__(256) void k_mlp(
    const float* __restrict__ Hin, int hstride,
    const float* __restrict__ W1, const float* __restrict__ b1,
    const float* __restrict__ W2, const float* __restrict__ b2,
    float* __restrict__ outb, float* __restrict__ dout,
    float* __restrict__ glast, int mode, int tstep)
{
    __shared__ __align__(16) float w1s[64 * 132];
    __shared__ __align__(16) float hs[16 * 132];
    __shared__ float h1s[16 * 68];
    __shared__ float w2s[128];
    __shared__ float b1s[64];
    __shared__ float b2s[2];

    int tid = threadIdx.x;
    int row0 = blockIdx.x * 16;

    for (int idx = tid; idx < 64 * 128; idx += 256) {
        int o = idx >> 7, k = idx & 127;
        w1s[o * 132 + k] = W1[idx];
    }
    for (int idx = tid; idx < 16 * 128; idx += 256) {
        int rr = idx >> 7, k = idx & 127;
        hs[rr * 132 + k] = Hin[(long)(row0 + rr) * hstride + k];
    }
    if (tid < 128) w2s[tid] = W2[tid];
    if (tid < 64)  b1s[tid] = b1[tid];
    if (tid < 2)   b2s[tid] = b2[tid];
    __syncthreads();

    #pragma unroll
    for (int p = 0; p < 4; p++) {
        int idx = p * 256 + tid;
        int o = idx & 63, rr = idx >> 6;
        const float* wp = w1s + o * 132;
        const float* hp = hs + rr * 132;
        float acc = b1s[o];
        #pragma unroll 8
        for (int k = 0; k < 128; k += 4) {
            float4 w4 = *(const float4*)(wp + k);
            float4 h4 = *(const float4*)(hp + k);
            acc = fmaf(w4.x, h4.x, acc);
            acc = fmaf(w4.y, h4.y, acc);
            acc = fmaf(w4.z, h4.z, acc);
            acc = fmaf(w4.w, h4.w, acc);
        }
        h1s[rr * 68 + o] = fmaxf(acc, 0.f);
    }
    __syncthreads();

    if (tid < 32) {
        int rr = tid >> 1, c = tid & 1;
        const float* hp = h1s + rr * 68;
        const float* wp = w2s + c * 64;
        float acc = b2s[c];
        #pragma unroll 8
        for (int k = 0; k < 64; k++) acc = fmaf(hp[k], wp[k], acc);
        float pred = softp(acc);
        int row = row0 + rr;
        if (mode == 0) {
            int t = row >> 10, b = row & 1023;
            if (t < 127) {
                long off = (long)b * 254 + t * 2 + c;
                #pragma unroll
                for (int s = 0; s < SS; s++)
                    outb[(long)s * ENC_SSTRIDE + off] = pred;
            } else {
                glast[b * 2 + c] = pred;
                #pragma unroll
                for (int s = 0; s < SS; s++)
                    outb[DEC_BASE + (long)((s << 10) | b) * 128 + c] = pred;
            }
        } else {
            dout[row * 2 + c] = pred;
            outb[DEC_BASE + (long)row * 128 + tstep * 2 + c] = pred;
        }
    }
}

// ---------------------------------------------------------------------------
// Reparameterization + decoder initial hidden states
// ---------------------------------------------------------------------------
__global__ void k_z(
    const float* __restrict__ hf0, const float* __restrict__ hf1,
    const float* __restrict__ eps, const float* __restrict__ feat,
    float* __restrict__ dh0, float* __restrict__ dh1)
{
    int idx = blockIdx.x * blockDim.x + threadIdx.x;
    if (idx >= SB * HD) return;
    int row = idx / HD, j = idx - row * HD;
    int s = row >> 10, b = row & 1023;
    float v0, v1;
    if (j < HH) {
        float m0 = hf0[b * HE + j],  lv0 = hf0[b * HE + HH + j];
        float m1 = hf1[b * HE + j],  lv1 = hf1[b * HE + HH + j];
        float e0 = eps[(((long)(s * 2 + 0) * BB + b) * HH) + j];
        float e1 = eps[(((long)(s * 2 + 1) * BB + b) * HH) + j];
        v0 = e0 * expf(0.5f * lv0) + m0;
        v1 = e1 * expf(0.5f * lv1) + m1;
    } else {
        float fc = feat[((long)b * TT + TENC) * FF + (j - HH)];
        v0 = fc; v1 = fc;
    }
    dh0[idx] = v0;
    dh1[idx] = v1;
}

__global__ void k_bcast_last(const float* __restrict__ last, float* __restrict__ dout)
{
    int i = blockIdx.x * blockDim.x + threadIdx.x;
    if (i < SB * 2) {
        int row = i >> 1, c = i & 1;
        dout[i] = last[((row & 1023) << 1) | c];
    }
}

__global__ void k_zero2(float* a, float* b, int n)
{
    int i = blockIdx.x * blockDim.x + threadIdx.x;
    if (i < n) { a[i] = 0.f; b[i] = 0.f; }
}

// ---------------------------------------------------------------------------
// Host orchestration (graph-capturable: kernel launches only)
// ---------------------------------------------------------------------------
extern "C" void kernel_launch(void* const* d_in, const int* in_sizes, int n_in,
                              void* d_out, int out_size)
{
    const float* x    = (const float*)d_in[0];
    const float* feat = (const float*)d_in[1];
    const int*   mask = (const int*)d_in[2];
    const float* eps  = (const float*)d_in[3];

    int base = (n_in > 7 && in_sizes[4] == 1) ? 7 : 4;
    const float* eWih0 = (const float*)d_in[base + 0];
    const float* eWhh0 = (const float*)d_in[base + 1];
    const float* ebih0 = (const float*)d_in[base + 2];
    const float* ebhh0 = (const float*)d_in[base + 3];
    const float* eWih1 = (const float*)d_in[base + 4];
    const float* eWhh1 = (const float*)d_in[base + 5];
    const float* ebih1 = (const float*)d_in[base + 6];
    const float* ebhh1 = (const float*)d_in[base + 7];
    const float* dWih0 = (const float*)d_in[base + 8];
    const float* dWhh0 = (const float*)d_in[base + 9];
    const float* dbih0 = (const float*)d_in[base + 10];
    const float* dbhh0 = (const float*)d_in[base + 11];
    const float* dWih1 = (const float*)d_in[base + 12];
    const float* dWhh1 = (const float*)d_in[base + 13];
    const float* dbih1 = (const float*)d_in[base + 14];
    const float* dbhh1 = (const float*)d_in[base + 15];
    const float* W1    = (const float*)d_in[base + 16];
    const float* b1    = (const float*)d_in[base + 17];
    const float* W2    = (const float*)d_in[base + 18];
    const float* b2    = (const float*)d_in[base + 19];

    float* outb = (float*)d_out;

    float *p_h0, *p_h1, *p_enc, *p_last, *p_dh0, *p_dh1, *p_dout;
    cudaGetSymbolAddress((void**)&p_h0,   g_h0);
    cudaGetSymbolAddress((void**)&p_h1,   g_h1);
    cudaGetSymbolAddress((void**)&p_enc,  g_enc);
    cudaGetSymbolAddress((void**)&p_last, g_last);
    cudaGetSymbolAddress((void**)&p_dh0,  g_dh0);
    cudaGetSymbolAddress((void**)&p_dh1,  g_dh1);
    cudaGetSymbolAddress((void**)&p_dout, g_dout);

    cudaFuncSetAttribute(k_gru, cudaFuncAttributeMaxDynamicSharedMemorySize, SM_BYTES);

    const int HSZ = BB * HE;
    const int DSZ = SB * HD;

    k_zero2<<<(HSZ + 255) / 256, 256>>>(p_h0, p_h1, HSZ);

    // ---------------- encoder scan ----------------
    float* h0c = p_h0;        float* h0n = p_h0 + HSZ;
    float* h1c = p_h1;        float* h1n = p_h1 + HSZ;
    dim3 egrid(BB / 32, HE / 32);   // (32, 8)
    for (int t = 0; t < TENC; t++) {
        k_gru<<<egrid, 256, SM_BYTES>>>(h0c, h0n,
                              x + (long)t * 2, 2, (long)TENC * 2,
                              feat + (long)t * FF, FF, (long)TT * FF,
                              eWih0, eWhh0, ebih0, ebhh0,
                              mask + t, TENC, (float*)nullptr, HE);
        k_gru<<<egrid, 256, SM_BYTES>>>(h1c, h1n,
                              h0n, HE, (long)HE,
                              (const float*)nullptr, 0, 0L,
                              eWih1, eWhh1, ebih1, ebhh1,
                              mask + t, TENC,
                              p_enc + (long)t * BB * HH, HE);
        float* tmp;
        tmp = h0c; h0c = h0n; h0n = tmp;
        tmp = h1c; h1c = h1n; h1n = tmp;
    }

    // ---------------- reparameterize + encoder MLP ----------------
    k_z<<<(SB * HD + 255) / 256, 256>>>(h0c, h1c, eps, feat, p_dh0, p_dh1);
    k_mlp<<<(TENC * BB) / 16, 256>>>(p_enc, HH, W1, b1, W2, b2,
                                     outb, (float*)nullptr, p_last, 0, 0);
    k_bcast_last<<<(SB * 2 + 255) / 256, 256>>>(p_last, p_dout);

    // ---------------- decoder scan ----------------
    float* d0c = p_dh0;       float* d0n = p_dh0 + DSZ;
    float* d1c = p_dh1;       float* d1n = p_dh1 + DSZ;
    dim3 dgrid(SB / 32, (HD + 31) / 32);   // (256, 5)
    for (int t = 1; t < TDEC; t++) {
        k_gru<<<dgrid, 256, SM_BYTES>>>(d0c, d0n,
                              p_dout, 2, 2L,
                              (const float*)nullptr, 0, 0L,
                              dWih0, dWhh0, dbih0, dbhh0,
                              (const int*)nullptr, 0, (float*)nullptr, HD);
        k_gru<<<dgrid, 256, SM_BYTES>>>(d1c, d1n,
                              d0n, HD, (long)HD,
                              (const float*)nullptr, 0, 0L,
                              dWih1, dWhh1, dbih1, dbhh1,
                              (const int*)nullptr, 0, (float*)nullptr, HD);
        k_mlp<<<SB / 16, 256>>>(d1n, HD, W1, b1, W2, b2,
                                outb, p_dout, (float*)nullptr, 1, t);
        float* tmp;
        tmp = d0c; d0c = d0n; d0n = tmp;
        tmp = d1c; d1c = d1n; d1n = tmp;
    }
}